// round 4
// baseline (speedup 1.0000x reference)
#include <cuda_runtime.h>
#include <cstdint>

#define B_   8
#define K_   19
#define C_   512
#define HW_  16384
#define SCH  1024                 // s-chunk staged in smem (per buffer)
#define NCHUNK (HW_ / SCH)        // 16
#define IPC  (SCH / 64)           // 16 inner iters per chunk
#define CC   4                    // c rows per warp
#define CT   32                   // c rows per block (8 warps per k-group)
#define NTHR 512                  // 16 warps: wg0 -> k[0,10), wg1 -> k[10,19)
#define SMEM_FLOATS (2 * K_ * SCH)

typedef unsigned long long u64;

__device__ __align__(16) float g_e[B_ * K_ * HW_];
__device__ float g_inv[B_ * K_];

// ---------------------------------------------------------------------------
// Kernel 1: e = exp(p - rowmax), inv = 1/sum(e). One block per (b,k) row.
// ---------------------------------------------------------------------------
__global__ __launch_bounds__(256) void softmax_k(const float* __restrict__ probs) {
    const int row = blockIdx.x;
    const float4* p4 = (const float4*)(probs + (size_t)row * HW_);
    float4* e4 = (float4*)(g_e + (size_t)row * HW_);
    const int tid = threadIdx.x;

    float4 v[16];
    float m = -1e30f;
#pragma unroll
    for (int i = 0; i < 16; i++) {
        v[i] = p4[tid + 256 * i];
        m = fmaxf(m, fmaxf(fmaxf(v[i].x, v[i].y), fmaxf(v[i].z, v[i].w)));
    }

    __shared__ float red[32];
#pragma unroll
    for (int off = 16; off; off >>= 1) m = fmaxf(m, __shfl_xor_sync(0xffffffffu, m, off));
    if ((tid & 31) == 0) red[tid >> 5] = m;
    __syncthreads();
    if (tid < 32) {
        float t = (tid < 8) ? red[tid] : -1e30f;
#pragma unroll
        for (int off = 4; off; off >>= 1) t = fmaxf(t, __shfl_xor_sync(0xffffffffu, t, off));
        if (tid == 0) red[0] = t;
    }
    __syncthreads();
    m = red[0];

    float s = 0.f;
#pragma unroll
    for (int i = 0; i < 16; i++) {
        float4 e;
        e.x = __expf(v[i].x - m);
        e.y = __expf(v[i].y - m);
        e.z = __expf(v[i].z - m);
        e.w = __expf(v[i].w - m);
        s += (e.x + e.y) + (e.z + e.w);
        e4[tid + 256 * i] = e;
    }

    __syncthreads();
#pragma unroll
    for (int off = 16; off; off >>= 1) s += __shfl_xor_sync(0xffffffffu, s, off);
    if ((tid & 31) == 0) red[tid >> 5] = s;
    __syncthreads();
    if (tid == 0) {
        float t = 0.f;
#pragma unroll
        for (int i = 0; i < 8; i++) t += red[i];
        g_inv[row] = 1.0f / t;
    }
}

// ---------------------------------------------------------------------------
// helpers
// ---------------------------------------------------------------------------
__device__ __forceinline__ void cp16(uint32_t saddr, const void* gaddr) {
    asm volatile("cp.async.cg.shared.global [%0], [%1], 16;" :: "r"(saddr), "l"(gaddr));
}
__device__ __forceinline__ void cp_commit() { asm volatile("cp.async.commit_group;"); }
template <int N>
__device__ __forceinline__ void cp_wait() {
    asm volatile("cp.async.wait_group %0;" :: "n"(N));
}

// one k-group's FMA work for a 64-s strip (straightline; ptxas schedules loads)
template <int KN, int KOFF>
__device__ __forceinline__ void fma_block(const float* ep, u64 (&acc)[10][CC],
                                          const u64 (&fA)[CC]) {
#pragma unroll
    for (int j = 0; j < KN; j++) {
        u64 e2 = *(const u64*)(ep + (KOFF + j) * SCH);
#pragma unroll
        for (int cc = 0; cc < CC; cc++)
            asm("fma.rn.f32x2 %0, %1, %2, %0;"
                : "+l"(acc[j][cc]) : "l"(e2), "l"(fA[cc]));
    }
}

// ---------------------------------------------------------------------------
// Kernel 2: out[b,c,k] = inv[b,k] * sum_s e[b,k,s] * f[b,c,s]
//   512 threads; warp-group 0 (warps 0-7) covers k 0..9, warp-group 1 covers
//   k 10..18. Halves the accumulator file -> 16 warps/SM (4/SMSP) for latency
//   hiding. e staged once in double-buffered smem (cp.async); f streamed with
//   distance-2 prefetch; packed fma.rn.f32x2 accumulators.
// ---------------------------------------------------------------------------
__global__ __launch_bounds__(NTHR, 1) void ctx_k(const float* __restrict__ feats,
                                                 float* __restrict__ out) {
    extern __shared__ float es[];                     // [2][K_][SCH]
    const int b    = blockIdx.y;
    const int tid  = threadIdx.x;
    const int lane = tid & 31;
    const int w    = tid >> 5;                        // 0..15
    const int wg   = w >> 3;                          // k-group
    const int wl   = w & 7;                           // warp within group
    const int c0   = blockIdx.x * CT + wl * CC;

    const float* erow = g_e + (size_t)b * K_ * HW_;
    const uint32_t smem_base = (uint32_t)__cvta_generic_to_shared(es);

    const u64* fbase = (const u64*)(feats + ((size_t)b * C_ + c0) * HW_) + lane;

    u64 acc[10][CC];
#pragma unroll
    for (int k = 0; k < 10; k++)
#pragma unroll
        for (int cc = 0; cc < CC; cc++) acc[k][cc] = 0ULL;

    // ---- stage chunk 0 into buffer 0 ----
    {
        const float4* src = (const float4*)erow;
#pragma unroll 1
        for (int idx = tid; idx < K_ * (SCH / 4); idx += NTHR) {
            int k = idx >> 8;
            int j = idx & (SCH / 4 - 1);
            cp16(smem_base + (uint32_t)(idx << 4), src + k * (HW_ / 4) + j);
        }
        cp_commit();
    }

    // ---- f prefetch (distance 2, continuous across chunk boundaries) ----
    u64 fA[CC], fB[CC];
#pragma unroll
    for (int cc = 0; cc < CC; cc++) fA[cc] = fbase[cc * (HW_ / 2)];
#pragma unroll
    for (int cc = 0; cc < CC; cc++) fB[cc] = fbase[cc * (HW_ / 2) + 32];

#pragma unroll 1
    for (int c = 0; c < NCHUNK; c++) {
        __syncthreads();                              // retire buffer (c+1)&1
        if (c + 1 < NCHUNK) {
            const float4* src = (const float4*)(erow + (c + 1) * SCH);
            const uint32_t boff = ((c + 1) & 1) * (K_ * SCH * 4);
#pragma unroll 1
            for (int idx = tid; idx < K_ * (SCH / 4); idx += NTHR) {
                int k = idx >> 8;
                int j = idx & (SCH / 4 - 1);
                cp16(smem_base + boff + (uint32_t)(idx << 4), src + k * (HW_ / 4) + j);
            }
            cp_commit();
            cp_wait<1>();                             // chunk c ready
        } else {
            cp_wait<0>();
        }
        __syncthreads();

        const float* esc = es + (c & 1) * (K_ * SCH);

#pragma unroll 1
        for (int ii = 0; ii < IPC; ii++) {
            const int i = c * IPC + ii;
            const int ip = (i + 2 < NCHUNK * IPC) ? (i + 2) : i;
            u64 fC[CC];
#pragma unroll
            for (int cc = 0; cc < CC; cc++)
                fC[cc] = fbase[cc * (HW_ / 2) + ip * 32];

            const float* ep = esc + ii * 64 + lane * 2;

            if (wg == 0) fma_block<10, 0>(ep, acc, fA);
            else         fma_block<9, 10>(ep, acc, fA);

#pragma unroll
            for (int cc = 0; cc < CC; cc++) { fA[cc] = fB[cc]; fB[cc] = fC[cc]; }
        }
    }

    // ---- epilogue: fold packed halves, warp-reduce over s-lanes, scale, store ----
    const int koff = wg * 10;
    const int kn   = wg ? 9 : 10;
    const float* invp = g_inv + b * K_;
    float* orow = out + ((size_t)b * C_ + c0) * K_;
#pragma unroll
    for (int j = 0; j < 10; j++) {
        if (j >= kn) break;
#pragma unroll
        for (int cc = 0; cc < CC; cc++) {
            unsigned int lo = (unsigned int)(acc[j][cc] & 0xffffffffULL);
            unsigned int hi = (unsigned int)(acc[j][cc] >> 32);
            float v = __uint_as_float(lo) + __uint_as_float(hi);
#pragma unroll
            for (int off = 16; off; off >>= 1)
                v += __shfl_xor_sync(0xffffffffu, v, off);
            if (lane == 0)
                orow[cc * K_ + koff + j] = v * invp[koff + j];
        }
    }
}

// ---------------------------------------------------------------------------
extern "C" void kernel_launch(void* const* d_in, const int* in_sizes, int n_in,
                              void* d_out, int out_size) {
    const float* feats = (const float*)d_in[0];   // (8, 512, 128, 128) fp32
    const float* probs = (const float*)d_in[1];   // (8, 19, 128, 128) fp32
    float* out = (float*)d_out;                   // (8, 512, 19, 1) fp32

    cudaFuncSetAttribute(ctx_k, cudaFuncAttributeMaxDynamicSharedMemorySize,
                         SMEM_FLOATS * (int)sizeof(float));

    softmax_k<<<B_ * K_, 256>>>(probs);
    ctx_k<<<dim3(C_ / CT, B_), NTHR, SMEM_FLOATS * sizeof(float)>>>(feats, out);
}